// round 3
// baseline (speedup 1.0000x reference)
#include <cuda_runtime.h>
#include <math.h>

#define N_USERS 50000
#define N_ENT   150000
#define NN      200000
#define NE      3200000
#define BATCH   4096

// Scratch (device globals; no allocation allowed)
__device__ float g_hn1[NN * 64];           // layer-1 neighbor aggregation
__device__ float g_h1 [NN * 64];           // layer-1 output (l2-normalized)
__device__ float g_hn2[NN * 64];           // layer-2 neighbor aggregation
__device__ float g_h2 [NN * 32];           // layer-2 output (l2-normalized)
__device__ unsigned char g_flag1[NN];      // nodes needing h1
__device__ unsigned char g_flag2[NN];      // nodes needing h2 / hn2

__device__ __forceinline__ void red_add_v4(float* addr, float4 v) {
    asm volatile("red.global.add.v4.f32 [%0], {%1,%2,%3,%4};"
                 :: "l"(addr), "f"(v.x), "f"(v.y), "f"(v.z), "f"(v.w)
                 : "memory");
}

// ---------------- flag kernels ----------------

__global__ void k_flags(const int* __restrict__ uids, const int* __restrict__ pids,
                        const int* __restrict__ nids) {
    int b = blockIdx.x * blockDim.x + threadIdx.x;
    if (b >= BATCH) return;
    int u = uids[b];
    int p = N_USERS + pids[b];
    int n = N_USERS + nids[b];
    g_flag2[u] = 1; g_flag1[u] = 1;
    g_flag2[p] = 1; g_flag1[p] = 1;
    g_flag2[n] = 1; g_flag1[n] = 1;
}

__global__ void k_flag_neighbors(const int* __restrict__ target,
                                 const int* __restrict__ neighbor) {
    int e = blockIdx.x * blockDim.x + threadIdx.x;
    if (e >= NE) return;
    if (g_flag2[target[e]]) g_flag1[neighbor[e]] = 1;
}

// ---------------- aggregation kernels ----------------
// tasks = NE * 16 (one float4 per task, 16 per edge)

__global__ void k_agg1(const float* __restrict__ user_w, const float* __restrict__ entity_w,
                       const float* __restrict__ values, const int* __restrict__ target,
                       const int* __restrict__ neighbor) {
    unsigned idx = blockIdx.x * blockDim.x + threadIdx.x;
    unsigned e = idx >> 4;
    unsigned c = idx & 15;
    if (e >= NE) return;
    int t = target[e];
    if (!g_flag1[t]) return;
    int nb = neighbor[e];
    float v = values[e];
    const float4* src = (nb < N_USERS)
        ? (const float4*)(user_w + (size_t)nb * 64)
        : (const float4*)(entity_w + (size_t)(nb - N_USERS) * 64);
    float4 m = src[c];
    m.x *= v; m.y *= v; m.z *= v; m.w *= v;
    red_add_v4(&g_hn1[(size_t)t * 64 + c * 4], m);
}

__global__ void k_agg2(const float* __restrict__ values, const int* __restrict__ target,
                       const int* __restrict__ neighbor) {
    unsigned idx = blockIdx.x * blockDim.x + threadIdx.x;
    unsigned e = idx >> 4;
    unsigned c = idx & 15;
    if (e >= NE) return;
    int t = target[e];
    if (!g_flag2[t]) return;
    int nb = neighbor[e];
    float v = values[e];
    const float4* src = (const float4*)(g_h1 + (size_t)nb * 64);
    float4 m = src[c];
    m.x *= v; m.y *= v; m.z *= v; m.w *= v;
    red_add_v4(&g_hn2[(size_t)t * 64 + c * 4], m);
}

// ---------------- dense transform kernels ----------------

// warp-per-row, 8 rows/block. 64 -> 64
__global__ void k_layer1(const float* __restrict__ user_w, const float* __restrict__ entity_w,
                         const float* __restrict__ W1, const float* __restrict__ b1,
                         const float* __restrict__ W2, const float* __restrict__ b2) {
    __shared__ float sW1[64 * 64];
    __shared__ float sW2[64 * 64];
    __shared__ float sS[8][64];
    __shared__ float sP[8][64];
    int tid = threadIdx.x;
    for (int i = tid; i < 64 * 64; i += 256) { sW1[i] = W1[i]; sW2[i] = W2[i]; }
    __syncthreads();
    int warp = tid >> 5, lane = tid & 31;
    int row = blockIdx.x * 8 + warp;
    if (row >= NN) return;
    if (!g_flag1[row]) return;
    const float* feat = (row < N_USERS) ? user_w + (size_t)row * 64
                                        : entity_w + (size_t)(row - N_USERS) * 64;
    const float* hn = g_hn1 + (size_t)row * 64;
    float f0 = feat[lane], f1 = feat[lane + 32];
    float n0 = hn[lane],   n1 = hn[lane + 32];
    sS[warp][lane]      = f0 + n0;
    sS[warp][lane + 32] = f1 + n1;
    sP[warp][lane]      = f0 * n0;
    sP[warp][lane + 32] = f1 * n1;
    __syncwarp();
    float a0 = b1[lane] + b2[lane];
    float a1 = b1[lane + 32] + b2[lane + 32];
#pragma unroll 16
    for (int k = 0; k < 64; k++) {
        float s = sS[warp][k], p = sP[warp][k];
        a0 += s * sW1[k * 64 + lane]      + p * sW2[k * 64 + lane];
        a1 += s * sW1[k * 64 + lane + 32] + p * sW2[k * 64 + lane + 32];
    }
    a0 = a0 > 0.f ? a0 : 0.01f * a0;
    a1 = a1 > 0.f ? a1 : 0.01f * a1;
    float ss = a0 * a0 + a1 * a1;
#pragma unroll
    for (int o = 16; o; o >>= 1) ss += __shfl_xor_sync(0xffffffffu, ss, o);
    float inv = 1.0f / fmaxf(sqrtf(ss), 1e-12f);
    g_h1[(size_t)row * 64 + lane]      = a0 * inv;
    g_h1[(size_t)row * 64 + lane + 32] = a1 * inv;
}

// warp-per-batch-slot (3*BATCH slots, duplicates benign: identical writes). 64 -> 32
__global__ void k_layer2(const int* __restrict__ uids, const int* __restrict__ pids,
                         const int* __restrict__ nids,
                         const float* __restrict__ W1, const float* __restrict__ b1,
                         const float* __restrict__ W2, const float* __restrict__ b2) {
    __shared__ float sW1[64 * 32];
    __shared__ float sW2[64 * 32];
    __shared__ float sS[8][64];
    __shared__ float sP[8][64];
    int tid = threadIdx.x;
    for (int i = tid; i < 64 * 32; i += 256) { sW1[i] = W1[i]; sW2[i] = W2[i]; }
    __syncthreads();
    int warp = tid >> 5, lane = tid & 31;
    int idx = blockIdx.x * 8 + warp;
    if (idx >= 3 * BATCH) return;
    int node;
    if (idx < BATCH)          node = uids[idx];
    else if (idx < 2 * BATCH) node = N_USERS + pids[idx - BATCH];
    else                      node = N_USERS + nids[idx - 2 * BATCH];
    const float* feat = g_h1  + (size_t)node * 64;
    const float* hn   = g_hn2 + (size_t)node * 64;
    float f0 = feat[lane], f1 = feat[lane + 32];
    float n0 = hn[lane],   n1 = hn[lane + 32];
    sS[warp][lane]      = f0 + n0;
    sS[warp][lane + 32] = f1 + n1;
    sP[warp][lane]      = f0 * n0;
    sP[warp][lane + 32] = f1 * n1;
    __syncwarp();
    float a = b1[lane] + b2[lane];
#pragma unroll 16
    for (int k = 0; k < 64; k++) {
        a += sS[warp][k] * sW1[k * 32 + lane] + sP[warp][k] * sW2[k * 32 + lane];
    }
    a = a > 0.f ? a : 0.01f * a;
    float ss = a * a;
#pragma unroll
    for (int o = 16; o; o >>= 1) ss += __shfl_xor_sync(0xffffffffu, ss, o);
    float inv = 1.0f / fmaxf(sqrtf(ss), 1e-12f);
    g_h2[(size_t)node * 32 + lane] = a * inv;
}

// ---------------- scoring ----------------
// warp per batch element; 160-dim dot for pos and neg.
__global__ void k_score(const float* __restrict__ user_w, const float* __restrict__ entity_w,
                        const int* __restrict__ uids, const int* __restrict__ pids,
                        const int* __restrict__ nids, float* __restrict__ out) {
    int tid = threadIdx.x;
    int warp = tid >> 5, lane = tid & 31;
    int b = blockIdx.x * 8 + warp;
    if (b >= BATCH) return;
    int u  = uids[b];
    int pe = pids[b];   // entity index
    int ne = nids[b];
    int pn = N_USERS + pe;  // node index
    int nn = N_USERS + ne;

    const float* fu = user_w + (size_t)u * 64;
    float u0 = fu[lane], u1 = fu[lane + 32];
    float h1u0 = g_h1[(size_t)u * 64 + lane], h1u1 = g_h1[(size_t)u * 64 + lane + 32];
    float h2u  = g_h2[(size_t)u * 32 + lane];

    const float* fp = entity_w + (size_t)pe * 64;
    float pos = u0 * fp[lane] + u1 * fp[lane + 32]
              + h1u0 * g_h1[(size_t)pn * 64 + lane] + h1u1 * g_h1[(size_t)pn * 64 + lane + 32]
              + h2u * g_h2[(size_t)pn * 32 + lane];

    const float* fn = entity_w + (size_t)ne * 64;
    float neg = u0 * fn[lane] + u1 * fn[lane + 32]
              + h1u0 * g_h1[(size_t)nn * 64 + lane] + h1u1 * g_h1[(size_t)nn * 64 + lane + 32]
              + h2u * g_h2[(size_t)nn * 32 + lane];

#pragma unroll
    for (int o = 16; o; o >>= 1) {
        pos += __shfl_xor_sync(0xffffffffu, pos, o);
        neg += __shfl_xor_sync(0xffffffffu, neg, o);
    }
    if (lane == 0) {
        out[b] = pos;
        out[BATCH + b] = neg;
    }
}

// ---------------- launch ----------------

extern "C" void kernel_launch(void* const* d_in, const int* in_sizes, int n_in,
                              void* d_out, int out_size) {
    const float* user_w   = (const float*)d_in[0];
    const float* entity_w = (const float*)d_in[1];
    const float* W1a = (const float*)d_in[2];
    const float* b1a = (const float*)d_in[3];
    const float* W2a = (const float*)d_in[4];
    const float* b2a = (const float*)d_in[5];
    const float* W1b = (const float*)d_in[6];
    const float* b1b = (const float*)d_in[7];
    const float* W2b = (const float*)d_in[8];
    const float* b2b = (const float*)d_in[9];
    const float* values   = (const float*)d_in[10];
    const int*   target   = (const int*)d_in[11];
    const int*   neighbor = (const int*)d_in[12];
    const int*   uids     = (const int*)d_in[13];
    const int*   pids     = (const int*)d_in[14];
    const int*   nids     = (const int*)d_in[15];
    float* out = (float*)d_out;

    void *hn1p, *hn2p, *f1p, *f2p;
    cudaGetSymbolAddress(&hn1p, g_hn1);
    cudaGetSymbolAddress(&hn2p, g_hn2);
    cudaGetSymbolAddress(&f1p, g_flag1);
    cudaGetSymbolAddress(&f2p, g_flag2);
    cudaMemsetAsync(hn1p, 0, sizeof(float) * (size_t)NN * 64, 0);
    cudaMemsetAsync(hn2p, 0, sizeof(float) * (size_t)NN * 64, 0);
    cudaMemsetAsync(f1p, 0, NN, 0);
    cudaMemsetAsync(f2p, 0, NN, 0);

    k_flags<<<(BATCH + 255) / 256, 256>>>(uids, pids, nids);
    k_flag_neighbors<<<(NE + 255) / 256, 256>>>(target, neighbor);

    unsigned agg_tasks = (unsigned)NE * 16u;
    k_agg1<<<(agg_tasks + 255) / 256, 256>>>(user_w, entity_w, values, target, neighbor);
    k_layer1<<<(NN + 7) / 8, 256>>>(user_w, entity_w, W1a, b1a, W2a, b2a);
    k_agg2<<<(agg_tasks + 255) / 256, 256>>>(values, target, neighbor);
    k_layer2<<<(3 * BATCH + 7) / 8, 256>>>(uids, pids, nids, W1b, b1b, W2b, b2b);
    k_score<<<(BATCH + 7) / 8, 256>>>(user_w, entity_w, uids, pids, nids, out);
}

// round 4
// speedup vs baseline: 1.1498x; 1.1498x over previous
#include <cuda_runtime.h>
#include <math.h>

#define N_USERS 50000
#define N_ENT   150000
#define NN      200000
#define NE      3200000
#define BATCH   4096

// Scratch (device globals; no allocation allowed)
__device__ float g_hn1[NN * 64];           // layer-1 neighbor aggregation
__device__ float g_h1 [NN * 64];           // layer-1 output (l2-normalized)
__device__ float g_hn2[NN * 64];           // layer-2 neighbor aggregation
__device__ float g_h2 [NN * 32];           // layer-2 output (l2-normalized)
__device__ unsigned char g_flag1[NN];      // nodes needing h1
__device__ unsigned char g_flag2[NN];      // nodes needing h2 / hn2
__device__ int g_list[NN];                 // compacted flag1 node list
__device__ int g_cnt;                      // list length

__device__ __forceinline__ void red_add_v4(float* addr, float4 v) {
    asm volatile("red.global.add.v4.f32 [%0], {%1,%2,%3,%4};"
                 :: "l"(addr), "f"(v.x), "f"(v.y), "f"(v.z), "f"(v.w)
                 : "memory");
}

// ---------------- flag kernels ----------------

__global__ void k_flags(const int* __restrict__ uids, const int* __restrict__ pids,
                        const int* __restrict__ nids) {
    int b = blockIdx.x * blockDim.x + threadIdx.x;
    if (b >= BATCH) return;
    int u = uids[b];
    int p = N_USERS + pids[b];
    int n = N_USERS + nids[b];
    g_flag2[u] = 1; g_flag1[u] = 1;
    g_flag2[p] = 1; g_flag1[p] = 1;
    g_flag2[n] = 1; g_flag1[n] = 1;
    // zero only the hn2 rows that will ever be accumulated/read (flag2 rows)
    float4 z = make_float4(0.f, 0.f, 0.f, 0.f);
    float4* ru = (float4*)(g_hn2 + (size_t)u * 64);
    float4* rp = (float4*)(g_hn2 + (size_t)p * 64);
    float4* rn = (float4*)(g_hn2 + (size_t)n * 64);
#pragma unroll
    for (int i = 0; i < 16; i++) { ru[i] = z; rp[i] = z; rn[i] = z; }
}

__global__ void k_flag_neighbors(const int* __restrict__ target,
                                 const int* __restrict__ neighbor) {
    int e = blockIdx.x * blockDim.x + threadIdx.x;
    if (e >= NE) return;
    if (g_flag2[target[e]]) g_flag1[neighbor[e]] = 1;
}

__global__ void k_build_list() {
    int n = blockIdx.x * blockDim.x + threadIdx.x;
    if (n >= NN) return;
    if (g_flag1[n]) {
        int p = atomicAdd(&g_cnt, 1);
        g_list[p] = n;
    }
}

// ---------------- aggregation kernels ----------------
// tasks = NE * 16 (one float4 per task, 16 per edge)

__global__ void k_agg1(const float* __restrict__ user_w, const float* __restrict__ entity_w,
                       const float* __restrict__ values, const int* __restrict__ target,
                       const int* __restrict__ neighbor) {
    unsigned idx = blockIdx.x * blockDim.x + threadIdx.x;
    unsigned e = idx >> 4;
    unsigned c = idx & 15;
    if (e >= NE) return;
    int t = target[e];
    if (!g_flag1[t]) return;
    int nb = neighbor[e];
    float v = values[e];
    const float4* src = (nb < N_USERS)
        ? (const float4*)(user_w + (size_t)nb * 64)
        : (const float4*)(entity_w + (size_t)(nb - N_USERS) * 64);
    float4 m = src[c];
    m.x *= v; m.y *= v; m.z *= v; m.w *= v;
    red_add_v4(&g_hn1[(size_t)t * 64 + c * 4], m);
}

__global__ void k_agg2(const float* __restrict__ values, const int* __restrict__ target,
                       const int* __restrict__ neighbor) {
    unsigned idx = blockIdx.x * blockDim.x + threadIdx.x;
    unsigned e = idx >> 4;
    unsigned c = idx & 15;
    if (e >= NE) return;
    int t = target[e];
    if (!g_flag2[t]) return;
    int nb = neighbor[e];
    float v = values[e];
    const float4* src = (const float4*)(g_h1 + (size_t)nb * 64);
    float4 m = src[c];
    m.x *= v; m.y *= v; m.z *= v; m.w *= v;
    red_add_v4(&g_hn2[(size_t)t * 64 + c * 4], m);
}

// ---------------- layer-1: block-tiled GEMM over compacted rows ----------------
// 32 rows per block, 256 threads. Dynamic smem layout (floats):
//   [0 : 4096)            sW1   64x64
//   [4096 : 8192)         sW2   64x64
//   [8192 : 8192+2304)    sS    64 x 36  (transposed: [k][row], padded stride 36)
//   [10496 : 12800)       sP    64 x 36
//   [12800 : 14848)       sH    32 x 64  (activated outputs)
//   [14848 : 14880)       sNode 32 ints
#define L1_SMEM_FLOATS (14880)

__global__ __launch_bounds__(256) void k_layer1(
        const float* __restrict__ user_w, const float* __restrict__ entity_w,
        const float* __restrict__ W1, const float* __restrict__ b1,
        const float* __restrict__ W2, const float* __restrict__ b2) {
    extern __shared__ float sm[];
    float* sW1 = sm;
    float* sW2 = sm + 4096;
    float* sS  = sm + 8192;    // [k*36 + row]
    float* sP  = sm + 10496;
    float* sH  = sm + 12800;   // [row*64 + col]
    int*   sNode = (int*)(sm + 14848);

    int tid = threadIdx.x;
    int base = blockIdx.x * 32;
    int cnt = g_cnt;
    if (base >= cnt) return;

    // load weights (once per block)
    {
        const float4* w1v = (const float4*)W1;
        const float4* w2v = (const float4*)W2;
        float4* s1v = (float4*)sW1;
        float4* s2v = (float4*)sW2;
#pragma unroll
        for (int i = 0; i < 4; i++) {
            s1v[tid + 256 * i] = w1v[tid + 256 * i];
            s2v[tid + 256 * i] = w2v[tid + 256 * i];
        }
    }

    // load 32 rows, build S = f+h, P = f*h transposed in smem
#pragma unroll
    for (int pass = 0; pass < 2; pass++) {
        int idx = pass * 256 + tid;
        int row = idx & 31;
        int q   = idx >> 5;      // 0..15 (float4 quad within the 64-dim row)
        int li  = base + row;
        float4 f = make_float4(0.f, 0.f, 0.f, 0.f);
        float4 h = f;
        int node = -1;
        if (li < cnt) {
            node = g_list[li];
            const float* fp = (node < N_USERS) ? user_w + (size_t)node * 64
                                               : entity_w + (size_t)(node - N_USERS) * 64;
            f = ((const float4*)fp)[q];
            h = ((const float4*)(g_hn1 + (size_t)node * 64))[q];
        }
        if (q == 0) sNode[row] = node;
        int k0 = q * 4;
        sS[(k0 + 0) * 36 + row] = f.x + h.x;
        sS[(k0 + 1) * 36 + row] = f.y + h.y;
        sS[(k0 + 2) * 36 + row] = f.z + h.z;
        sS[(k0 + 3) * 36 + row] = f.w + h.w;
        sP[(k0 + 0) * 36 + row] = f.x * h.x;
        sP[(k0 + 1) * 36 + row] = f.y * h.y;
        sP[(k0 + 2) * 36 + row] = f.z * h.z;
        sP[(k0 + 3) * 36 + row] = f.w * h.w;
    }
    __syncthreads();

    // compute: thread = (col 0..63, rg 0..3); rows rg*8..rg*8+7, one column
    int col = tid & 63;
    int rg  = tid >> 6;
    float acc[8];
    float bb = b1[col] + b2[col];
#pragma unroll
    for (int r = 0; r < 8; r++) acc[r] = bb;

#pragma unroll 8
    for (int k = 0; k < 64; k++) {
        float w1 = sW1[k * 64 + col];
        float w2 = sW2[k * 64 + col];
        const float* sk = sS + k * 36 + rg * 8;
        const float* pk = sP + k * 36 + rg * 8;
        float4 sa = *(const float4*)(sk);
        float4 sb = *(const float4*)(sk + 4);
        float4 pa = *(const float4*)(pk);
        float4 pb = *(const float4*)(pk + 4);
        acc[0] += sa.x * w1 + pa.x * w2;
        acc[1] += sa.y * w1 + pa.y * w2;
        acc[2] += sa.z * w1 + pa.z * w2;
        acc[3] += sa.w * w1 + pa.w * w2;
        acc[4] += sb.x * w1 + pb.x * w2;
        acc[5] += sb.y * w1 + pb.y * w2;
        acc[6] += sb.z * w1 + pb.z * w2;
        acc[7] += sb.w * w1 + pb.w * w2;
    }

    // leaky relu -> smem
#pragma unroll
    for (int r = 0; r < 8; r++) {
        float a = acc[r];
        a = a > 0.f ? a : 0.01f * a;
        sH[(rg * 8 + r) * 64 + col] = a;
    }
    __syncthreads();

    // l2 normalize + store: warp w handles rows w*4 .. w*4+3
    int warp = tid >> 5, lane = tid & 31;
#pragma unroll
    for (int j = 0; j < 4; j++) {
        int row = warp * 4 + j;
        int node = sNode[row];
        float a0 = sH[row * 64 + lane];
        float a1 = sH[row * 64 + lane + 32];
        float ss = a0 * a0 + a1 * a1;
#pragma unroll
        for (int o = 16; o; o >>= 1) ss += __shfl_xor_sync(0xffffffffu, ss, o);
        if (node >= 0) {
            float inv = 1.0f / fmaxf(sqrtf(ss), 1e-12f);
            g_h1[(size_t)node * 64 + lane]      = a0 * inv;
            g_h1[(size_t)node * 64 + lane + 32] = a1 * inv;
        }
    }
}

// ---------------- layer-2 (batch rows only) ----------------

__global__ void k_layer2(const int* __restrict__ uids, const int* __restrict__ pids,
                         const int* __restrict__ nids,
                         const float* __restrict__ W1, const float* __restrict__ b1,
                         const float* __restrict__ W2, const float* __restrict__ b2) {
    __shared__ float sW1[64 * 32];
    __shared__ float sW2[64 * 32];
    __shared__ float sS[8][64];
    __shared__ float sP[8][64];
    int tid = threadIdx.x;
    for (int i = tid; i < 64 * 32; i += 256) { sW1[i] = W1[i]; sW2[i] = W2[i]; }
    __syncthreads();
    int warp = tid >> 5, lane = tid & 31;
    int idx = blockIdx.x * 8 + warp;
    if (idx >= 3 * BATCH) return;
    int node;
    if (idx < BATCH)          node = uids[idx];
    else if (idx < 2 * BATCH) node = N_USERS + pids[idx - BATCH];
    else                      node = N_USERS + nids[idx - 2 * BATCH];
    const float* feat = g_h1  + (size_t)node * 64;
    const float* hn   = g_hn2 + (size_t)node * 64;
    float f0 = feat[lane], f1 = feat[lane + 32];
    float n0 = hn[lane],   n1 = hn[lane + 32];
    sS[warp][lane]      = f0 + n0;
    sS[warp][lane + 32] = f1 + n1;
    sP[warp][lane]      = f0 * n0;
    sP[warp][lane + 32] = f1 * n1;
    __syncwarp();
    float a = b1[lane] + b2[lane];
#pragma unroll 16
    for (int k = 0; k < 64; k++) {
        a += sS[warp][k] * sW1[k * 32 + lane] + sP[warp][k] * sW2[k * 32 + lane];
    }
    a = a > 0.f ? a : 0.01f * a;
    float ss = a * a;
#pragma unroll
    for (int o = 16; o; o >>= 1) ss += __shfl_xor_sync(0xffffffffu, ss, o);
    float inv = 1.0f / fmaxf(sqrtf(ss), 1e-12f);
    g_h2[(size_t)node * 32 + lane] = a * inv;
}

// ---------------- scoring ----------------

__global__ void k_score(const float* __restrict__ user_w, const float* __restrict__ entity_w,
                        const int* __restrict__ uids, const int* __restrict__ pids,
                        const int* __restrict__ nids, float* __restrict__ out) {
    int tid = threadIdx.x;
    int warp = tid >> 5, lane = tid & 31;
    int b = blockIdx.x * 8 + warp;
    if (b >= BATCH) return;
    int u  = uids[b];
    int pe = pids[b];
    int ne = nids[b];
    int pn = N_USERS + pe;
    int nn = N_USERS + ne;

    const float* fu = user_w + (size_t)u * 64;
    float u0 = fu[lane], u1 = fu[lane + 32];
    float h1u0 = g_h1[(size_t)u * 64 + lane], h1u1 = g_h1[(size_t)u * 64 + lane + 32];
    float h2u  = g_h2[(size_t)u * 32 + lane];

    const float* fp = entity_w + (size_t)pe * 64;
    float pos = u0 * fp[lane] + u1 * fp[lane + 32]
              + h1u0 * g_h1[(size_t)pn * 64 + lane] + h1u1 * g_h1[(size_t)pn * 64 + lane + 32]
              + h2u * g_h2[(size_t)pn * 32 + lane];

    const float* fn = entity_w + (size_t)ne * 64;
    float neg = u0 * fn[lane] + u1 * fn[lane + 32]
              + h1u0 * g_h1[(size_t)nn * 64 + lane] + h1u1 * g_h1[(size_t)nn * 64 + lane + 32]
              + h2u * g_h2[(size_t)nn * 32 + lane];

#pragma unroll
    for (int o = 16; o; o >>= 1) {
        pos += __shfl_xor_sync(0xffffffffu, pos, o);
        neg += __shfl_xor_sync(0xffffffffu, neg, o);
    }
    if (lane == 0) {
        out[b] = pos;
        out[BATCH + b] = neg;
    }
}

// ---------------- launch ----------------

extern "C" void kernel_launch(void* const* d_in, const int* in_sizes, int n_in,
                              void* d_out, int out_size) {
    const float* user_w   = (const float*)d_in[0];
    const float* entity_w = (const float*)d_in[1];
    const float* W1a = (const float*)d_in[2];
    const float* b1a = (const float*)d_in[3];
    const float* W2a = (const float*)d_in[4];
    const float* b2a = (const float*)d_in[5];
    const float* W1b = (const float*)d_in[6];
    const float* b1b = (const float*)d_in[7];
    const float* W2b = (const float*)d_in[8];
    const float* b2b = (const float*)d_in[9];
    const float* values   = (const float*)d_in[10];
    const int*   target   = (const int*)d_in[11];
    const int*   neighbor = (const int*)d_in[12];
    const int*   uids     = (const int*)d_in[13];
    const int*   pids     = (const int*)d_in[14];
    const int*   nids     = (const int*)d_in[15];
    float* out = (float*)d_out;

    static bool attr_set = false;
    if (!attr_set) {
        cudaFuncSetAttribute(k_layer1, cudaFuncAttributeMaxDynamicSharedMemorySize,
                             L1_SMEM_FLOATS * (int)sizeof(float));
        attr_set = true;
    }

    void *hn1p, *f1p, *f2p, *cntp;
    cudaGetSymbolAddress(&hn1p, g_hn1);
    cudaGetSymbolAddress(&f1p, g_flag1);
    cudaGetSymbolAddress(&f2p, g_flag2);
    cudaGetSymbolAddress(&cntp, g_cnt);
    cudaMemsetAsync(hn1p, 0, sizeof(float) * (size_t)NN * 64, 0);
    cudaMemsetAsync(f1p, 0, NN, 0);
    cudaMemsetAsync(f2p, 0, NN, 0);
    cudaMemsetAsync(cntp, 0, sizeof(int), 0);

    k_flags<<<(BATCH + 255) / 256, 256>>>(uids, pids, nids);
    k_flag_neighbors<<<(NE + 255) / 256, 256>>>(target, neighbor);
    k_build_list<<<(NN + 255) / 256, 256>>>();

    unsigned agg_tasks = (unsigned)NE * 16u;
    k_agg1<<<(agg_tasks + 255) / 256, 256>>>(user_w, entity_w, values, target, neighbor);
    k_layer1<<<(NN + 31) / 32, 256, L1_SMEM_FLOATS * sizeof(float)>>>(
        user_w, entity_w, W1a, b1a, W2a, b2a);
    k_agg2<<<(agg_tasks + 255) / 256, 256>>>(values, target, neighbor);
    k_layer2<<<(3 * BATCH + 7) / 8, 256>>>(uids, pids, nids, W1b, b1b, W2b, b2b);
    k_score<<<(BATCH + 7) / 8, 256>>>(user_w, entity_w, uids, pids, nids, out);
}

// round 5
// speedup vs baseline: 2.3247x; 2.0218x over previous
#include <cuda_runtime.h>
#include <math.h>

#define N_USERS 50000
#define N_ENT   150000
#define NN      200000
#define NE      3200000
#define BATCH   4096
#define NPARTS  196        // ceil(NN / 1024)

// Scratch (device globals; no allocation allowed)
__device__ float g_hn1[NN * 64];
__device__ float g_h1 [NN * 64];
__device__ float g_hn2[NN * 64];
__device__ float g_h2 [NN * 32];
__device__ unsigned char g_flag1[NN];
__device__ unsigned char g_flag2[NN];
__device__ int g_list[NN];
__device__ int g_cnt;
// CSR (flag1-filtered)
__device__ int  g_counts[NN];
__device__ int  g_offs[NN];
__device__ int  g_cursor[NN];
__device__ int2 g_csr[NE];          // (neighbor, value-as-int)
__device__ int  g_part[256];
__device__ int  g_part_offs[256];

// ---------------- flag kernels ----------------

__global__ void k_flags(const int* __restrict__ uids, const int* __restrict__ pids,
                        const int* __restrict__ nids) {
    int b = blockIdx.x * blockDim.x + threadIdx.x;
    if (b >= BATCH) return;
    int u = uids[b];
    int p = N_USERS + pids[b];
    int n = N_USERS + nids[b];
    g_flag2[u] = 1; g_flag1[u] = 1;
    g_flag2[p] = 1; g_flag1[p] = 1;
    g_flag2[n] = 1; g_flag1[n] = 1;
}

__global__ void k_flag_neighbors(const int* __restrict__ target,
                                 const int* __restrict__ neighbor) {
    int e = blockIdx.x * blockDim.x + threadIdx.x;
    if (e >= NE) return;
    if (g_flag2[target[e]]) g_flag1[neighbor[e]] = 1;
}

__global__ void k_build_list() {
    int n = blockIdx.x * blockDim.x + threadIdx.x;
    if (n >= NN) return;
    if (g_flag1[n]) {
        int p = atomicAdd(&g_cnt, 1);
        g_list[p] = n;
    }
}

// ---------------- CSR build ----------------

__global__ void k_count(const int* __restrict__ target) {
    int e = blockIdx.x * blockDim.x + threadIdx.x;
    if (e >= NE) return;
    int t = target[e];
    if (g_flag1[t]) atomicAdd(&g_counts[t], 1);
}

__global__ void k_scan1() {
    int i = blockIdx.x * 1024 + threadIdx.x;
    int x = (i < NN) ? g_counts[i] : 0;
#pragma unroll
    for (int o = 16; o; o >>= 1) x += __shfl_xor_sync(0xffffffffu, x, o);
    __shared__ int ws[32];
    if ((threadIdx.x & 31) == 0) ws[threadIdx.x >> 5] = x;
    __syncthreads();
    if (threadIdx.x < 32) {
        int s = ws[threadIdx.x];
#pragma unroll
        for (int o = 16; o; o >>= 1) s += __shfl_xor_sync(0xffffffffu, s, o);
        if (threadIdx.x == 0) g_part[blockIdx.x] = s;
    }
}

__global__ void k_scan2() {   // single block, 256 threads, scan NPARTS partials
    int tid = threadIdx.x;
    int lane = tid & 31, w = tid >> 5;
    int x = (tid < NPARTS) ? g_part[tid] : 0;
    int v = x;
#pragma unroll
    for (int o = 1; o < 32; o <<= 1) {
        int t = __shfl_up_sync(0xffffffffu, v, o);
        if (lane >= o) v += t;
    }
    __shared__ int ws[8];
    if (lane == 31) ws[w] = v;
    __syncthreads();
    if (w == 0 && lane < 8) {
        int s = ws[lane];
#pragma unroll
        for (int o = 1; o < 8; o <<= 1) {
            int t = __shfl_up_sync(0xffu, s, o);
            if (lane >= o) s += t;
        }
        ws[lane] = s;
    }
    __syncthreads();
    int excl = v - x + (w > 0 ? ws[w - 1] : 0);
    if (tid < NPARTS) g_part_offs[tid] = excl;
}

__global__ void k_scan3() {
    int tid = threadIdx.x;
    int i = blockIdx.x * 1024 + tid;
    int lane = tid & 31, w = tid >> 5;
    int x = (i < NN) ? g_counts[i] : 0;
    int v = x;
#pragma unroll
    for (int o = 1; o < 32; o <<= 1) {
        int t = __shfl_up_sync(0xffffffffu, v, o);
        if (lane >= o) v += t;
    }
    __shared__ int ws[32];
    if (lane == 31) ws[w] = v;
    __syncthreads();
    if (w == 0) {
        int s = ws[lane];
#pragma unroll
        for (int o = 1; o < 32; o <<= 1) {
            int t = __shfl_up_sync(0xffffffffu, s, o);
            if (lane >= o) s += t;
        }
        ws[lane] = s;
    }
    __syncthreads();
    int excl = v - x + (w > 0 ? ws[w - 1] : 0) + g_part_offs[blockIdx.x];
    if (i < NN) { g_offs[i] = excl; g_cursor[i] = excl; }
}

__global__ void k_scatter(const int* __restrict__ target, const int* __restrict__ neighbor,
                          const float* __restrict__ values) {
    int e = blockIdx.x * blockDim.x + threadIdx.x;
    if (e >= NE) return;
    int t = target[e];
    if (!g_flag1[t]) return;
    int p = atomicAdd(&g_cursor[t], 1);
    g_csr[p] = make_int2(neighbor[e], __float_as_int(values[e]));
}

// ---------------- CSR aggregation (no atomics) ----------------
// warp per node; lane owns dims {lane, lane+32}; 4 edges per inner iter for MLP.

__global__ __launch_bounds__(256) void k_agg1_csr(const float* __restrict__ user_w,
                                                  const float* __restrict__ entity_w) {
    int tid = threadIdx.x, lane = tid & 31, warp = tid >> 5;
    int li = blockIdx.x * 8 + warp;
    if (li >= g_cnt) return;
    int node = g_list[li];
    int beg = g_offs[node];
    int deg = g_counts[node];
    float acc0 = 0.f, acc1 = 0.f;
    for (int j = 0; j < deg; j += 32) {
        int2 ev = make_int2(0, 0);
        if (j + lane < deg) ev = g_csr[beg + j + lane];
        int rem = deg - j; if (rem > 32) rem = 32;
        int remR = (rem + 3) & ~3;
        for (int s = 0; s < remR; s += 4) {
            int nb0 = __shfl_sync(0xffffffffu, ev.x, s);
            int nb1 = __shfl_sync(0xffffffffu, ev.x, s + 1);
            int nb2 = __shfl_sync(0xffffffffu, ev.x, s + 2);
            int nb3 = __shfl_sync(0xffffffffu, ev.x, s + 3);
            float v0 = __int_as_float(__shfl_sync(0xffffffffu, ev.y, s));
            float v1 = __int_as_float(__shfl_sync(0xffffffffu, ev.y, s + 1));
            float v2 = __int_as_float(__shfl_sync(0xffffffffu, ev.y, s + 2));
            float v3 = __int_as_float(__shfl_sync(0xffffffffu, ev.y, s + 3));
            const float* p0 = (nb0 < N_USERS) ? user_w + (size_t)nb0 * 64 : entity_w + (size_t)(nb0 - N_USERS) * 64;
            const float* p1 = (nb1 < N_USERS) ? user_w + (size_t)nb1 * 64 : entity_w + (size_t)(nb1 - N_USERS) * 64;
            const float* p2 = (nb2 < N_USERS) ? user_w + (size_t)nb2 * 64 : entity_w + (size_t)(nb2 - N_USERS) * 64;
            const float* p3 = (nb3 < N_USERS) ? user_w + (size_t)nb3 * 64 : entity_w + (size_t)(nb3 - N_USERS) * 64;
            float a0 = p0[lane], b0 = p0[lane + 32];
            float a1 = p1[lane], b1 = p1[lane + 32];
            float a2 = p2[lane], b2 = p2[lane + 32];
            float a3 = p3[lane], b3 = p3[lane + 32];
            acc0 += v0 * a0; acc1 += v0 * b0;
            acc0 += v1 * a1; acc1 += v1 * b1;
            acc0 += v2 * a2; acc1 += v2 * b2;
            acc0 += v3 * a3; acc1 += v3 * b3;
        }
    }
    g_hn1[(size_t)node * 64 + lane]      = acc0;
    g_hn1[(size_t)node * 64 + lane + 32] = acc1;
}

__global__ __launch_bounds__(256) void k_agg2_csr(const int* __restrict__ uids,
                                                  const int* __restrict__ pids,
                                                  const int* __restrict__ nids) {
    int tid = threadIdx.x, lane = tid & 31, warp = tid >> 5;
    int idx = blockIdx.x * 8 + warp;
    if (idx >= 3 * BATCH) return;
    int node;
    if (idx < BATCH)          node = uids[idx];
    else if (idx < 2 * BATCH) node = N_USERS + pids[idx - BATCH];
    else                      node = N_USERS + nids[idx - 2 * BATCH];
    int beg = g_offs[node];
    int deg = g_counts[node];
    float acc0 = 0.f, acc1 = 0.f;
    for (int j = 0; j < deg; j += 32) {
        int2 ev = make_int2(0, 0);
        if (j + lane < deg) ev = g_csr[beg + j + lane];
        int rem = deg - j; if (rem > 32) rem = 32;
        int remR = (rem + 3) & ~3;
        for (int s = 0; s < remR; s += 4) {
            int nb0 = __shfl_sync(0xffffffffu, ev.x, s);
            int nb1 = __shfl_sync(0xffffffffu, ev.x, s + 1);
            int nb2 = __shfl_sync(0xffffffffu, ev.x, s + 2);
            int nb3 = __shfl_sync(0xffffffffu, ev.x, s + 3);
            float v0 = __int_as_float(__shfl_sync(0xffffffffu, ev.y, s));
            float v1 = __int_as_float(__shfl_sync(0xffffffffu, ev.y, s + 1));
            float v2 = __int_as_float(__shfl_sync(0xffffffffu, ev.y, s + 2));
            float v3 = __int_as_float(__shfl_sync(0xffffffffu, ev.y, s + 3));
            const float* p0 = g_h1 + (size_t)nb0 * 64;
            const float* p1 = g_h1 + (size_t)nb1 * 64;
            const float* p2 = g_h1 + (size_t)nb2 * 64;
            const float* p3 = g_h1 + (size_t)nb3 * 64;
            float a0 = p0[lane], b0 = p0[lane + 32];
            float a1 = p1[lane], b1 = p1[lane + 32];
            float a2 = p2[lane], b2 = p2[lane + 32];
            float a3 = p3[lane], b3 = p3[lane + 32];
            acc0 += v0 * a0; acc1 += v0 * b0;
            acc0 += v1 * a1; acc1 += v1 * b1;
            acc0 += v2 * a2; acc1 += v2 * b2;
            acc0 += v3 * a3; acc1 += v3 * b3;
        }
    }
    g_hn2[(size_t)node * 64 + lane]      = acc0;
    g_hn2[(size_t)node * 64 + lane + 32] = acc1;
}

// ---------------- layer-1: block-tiled GEMM over compacted rows ----------------
#define L1_SMEM_FLOATS (14880)

__global__ __launch_bounds__(256) void k_layer1(
        const float* __restrict__ user_w, const float* __restrict__ entity_w,
        const float* __restrict__ W1, const float* __restrict__ b1,
        const float* __restrict__ W2, const float* __restrict__ b2) {
    extern __shared__ float sm[];
    float* sW1 = sm;
    float* sW2 = sm + 4096;
    float* sS  = sm + 8192;    // [k*36 + row]
    float* sP  = sm + 10496;
    float* sH  = sm + 12800;   // [row*64 + col]
    int*   sNode = (int*)(sm + 14848);

    int tid = threadIdx.x;
    int base = blockIdx.x * 32;
    int cnt = g_cnt;
    if (base >= cnt) return;

    {
        const float4* w1v = (const float4*)W1;
        const float4* w2v = (const float4*)W2;
        float4* s1v = (float4*)sW1;
        float4* s2v = (float4*)sW2;
#pragma unroll
        for (int i = 0; i < 4; i++) {
            s1v[tid + 256 * i] = w1v[tid + 256 * i];
            s2v[tid + 256 * i] = w2v[tid + 256 * i];
        }
    }

#pragma unroll
    for (int pass = 0; pass < 2; pass++) {
        int idx = pass * 256 + tid;
        int row = idx & 31;
        int q   = idx >> 5;
        int li  = base + row;
        float4 f = make_float4(0.f, 0.f, 0.f, 0.f);
        float4 h = f;
        int node = -1;
        if (li < cnt) {
            node = g_list[li];
            const float* fp = (node < N_USERS) ? user_w + (size_t)node * 64
                                               : entity_w + (size_t)(node - N_USERS) * 64;
            f = ((const float4*)fp)[q];
            h = ((const float4*)(g_hn1 + (size_t)node * 64))[q];
        }
        if (q == 0) sNode[row] = node;
        int k0 = q * 4;
        sS[(k0 + 0) * 36 + row] = f.x + h.x;
        sS[(k0 + 1) * 36 + row] = f.y + h.y;
        sS[(k0 + 2) * 36 + row] = f.z + h.z;
        sS[(k0 + 3) * 36 + row] = f.w + h.w;
        sP[(k0 + 0) * 36 + row] = f.x * h.x;
        sP[(k0 + 1) * 36 + row] = f.y * h.y;
        sP[(k0 + 2) * 36 + row] = f.z * h.z;
        sP[(k0 + 3) * 36 + row] = f.w * h.w;
    }
    __syncthreads();

    int col = tid & 63;
    int rg  = tid >> 6;
    float acc[8];
    float bb = b1[col] + b2[col];
#pragma unroll
    for (int r = 0; r < 8; r++) acc[r] = bb;

#pragma unroll 8
    for (int k = 0; k < 64; k++) {
        float w1 = sW1[k * 64 + col];
        float w2 = sW2[k * 64 + col];
        const float* sk = sS + k * 36 + rg * 8;
        const float* pk = sP + k * 36 + rg * 8;
        float4 sa = *(const float4*)(sk);
        float4 sb = *(const float4*)(sk + 4);
        float4 pa = *(const float4*)(pk);
        float4 pb = *(const float4*)(pk + 4);
        acc[0] += sa.x * w1 + pa.x * w2;
        acc[1] += sa.y * w1 + pa.y * w2;
        acc[2] += sa.z * w1 + pa.z * w2;
        acc[3] += sa.w * w1 + pa.w * w2;
        acc[4] += sb.x * w1 + pb.x * w2;
        acc[5] += sb.y * w1 + pb.y * w2;
        acc[6] += sb.z * w1 + pb.z * w2;
        acc[7] += sb.w * w1 + pb.w * w2;
    }

#pragma unroll
    for (int r = 0; r < 8; r++) {
        float a = acc[r];
        a = a > 0.f ? a : 0.01f * a;
        sH[(rg * 8 + r) * 64 + col] = a;
    }
    __syncthreads();

    int warp = tid >> 5, lane = tid & 31;
#pragma unroll
    for (int j = 0; j < 4; j++) {
        int row = warp * 4 + j;
        int node = sNode[row];
        float a0 = sH[row * 64 + lane];
        float a1 = sH[row * 64 + lane + 32];
        float ss = a0 * a0 + a1 * a1;
#pragma unroll
        for (int o = 16; o; o >>= 1) ss += __shfl_xor_sync(0xffffffffu, ss, o);
        if (node >= 0) {
            float inv = 1.0f / fmaxf(sqrtf(ss), 1e-12f);
            g_h1[(size_t)node * 64 + lane]      = a0 * inv;
            g_h1[(size_t)node * 64 + lane + 32] = a1 * inv;
        }
    }
}

// ---------------- layer-2 (batch rows only) ----------------

__global__ void k_layer2(const int* __restrict__ uids, const int* __restrict__ pids,
                         const int* __restrict__ nids,
                         const float* __restrict__ W1, const float* __restrict__ b1,
                         const float* __restrict__ W2, const float* __restrict__ b2) {
    __shared__ float sW1[64 * 32];
    __shared__ float sW2[64 * 32];
    __shared__ float sS[8][64];
    __shared__ float sP[8][64];
    int tid = threadIdx.x;
    for (int i = tid; i < 64 * 32; i += 256) { sW1[i] = W1[i]; sW2[i] = W2[i]; }
    __syncthreads();
    int warp = tid >> 5, lane = tid & 31;
    int idx = blockIdx.x * 8 + warp;
    if (idx >= 3 * BATCH) return;
    int node;
    if (idx < BATCH)          node = uids[idx];
    else if (idx < 2 * BATCH) node = N_USERS + pids[idx - BATCH];
    else                      node = N_USERS + nids[idx - 2 * BATCH];
    const float* feat = g_h1  + (size_t)node * 64;
    const float* hn   = g_hn2 + (size_t)node * 64;
    float f0 = feat[lane], f1 = feat[lane + 32];
    float n0 = hn[lane],   n1 = hn[lane + 32];
    sS[warp][lane]      = f0 + n0;
    sS[warp][lane + 32] = f1 + n1;
    sP[warp][lane]      = f0 * n0;
    sP[warp][lane + 32] = f1 * n1;
    __syncwarp();
    float a = b1[lane] + b2[lane];
#pragma unroll 16
    for (int k = 0; k < 64; k++) {
        a += sS[warp][k] * sW1[k * 32 + lane] + sP[warp][k] * sW2[k * 32 + lane];
    }
    a = a > 0.f ? a : 0.01f * a;
    float ss = a * a;
#pragma unroll
    for (int o = 16; o; o >>= 1) ss += __shfl_xor_sync(0xffffffffu, ss, o);
    float inv = 1.0f / fmaxf(sqrtf(ss), 1e-12f);
    g_h2[(size_t)node * 32 + lane] = a * inv;
}

// ---------------- scoring ----------------

__global__ void k_score(const float* __restrict__ user_w, const float* __restrict__ entity_w,
                        const int* __restrict__ uids, const int* __restrict__ pids,
                        const int* __restrict__ nids, float* __restrict__ out) {
    int tid = threadIdx.x;
    int warp = tid >> 5, lane = tid & 31;
    int b = blockIdx.x * 8 + warp;
    if (b >= BATCH) return;
    int u  = uids[b];
    int pe = pids[b];
    int ne = nids[b];
    int pn = N_USERS + pe;
    int nn = N_USERS + ne;

    const float* fu = user_w + (size_t)u * 64;
    float u0 = fu[lane], u1 = fu[lane + 32];
    float h1u0 = g_h1[(size_t)u * 64 + lane], h1u1 = g_h1[(size_t)u * 64 + lane + 32];
    float h2u  = g_h2[(size_t)u * 32 + lane];

    const float* fp = entity_w + (size_t)pe * 64;
    float pos = u0 * fp[lane] + u1 * fp[lane + 32]
              + h1u0 * g_h1[(size_t)pn * 64 + lane] + h1u1 * g_h1[(size_t)pn * 64 + lane + 32]
              + h2u * g_h2[(size_t)pn * 32 + lane];

    const float* fn = entity_w + (size_t)ne * 64;
    float neg = u0 * fn[lane] + u1 * fn[lane + 32]
              + h1u0 * g_h1[(size_t)nn * 64 + lane] + h1u1 * g_h1[(size_t)nn * 64 + lane + 32]
              + h2u * g_h2[(size_t)nn * 32 + lane];

#pragma unroll
    for (int o = 16; o; o >>= 1) {
        pos += __shfl_xor_sync(0xffffffffu, pos, o);
        neg += __shfl_xor_sync(0xffffffffu, neg, o);
    }
    if (lane == 0) {
        out[b] = pos;
        out[BATCH + b] = neg;
    }
}

// ---------------- launch ----------------

extern "C" void kernel_launch(void* const* d_in, const int* in_sizes, int n_in,
                              void* d_out, int out_size) {
    const float* user_w   = (const float*)d_in[0];
    const float* entity_w = (const float*)d_in[1];
    const float* W1a = (const float*)d_in[2];
    const float* b1a = (const float*)d_in[3];
    const float* W2a = (const float*)d_in[4];
    const float* b2a = (const float*)d_in[5];
    const float* W1b = (const float*)d_in[6];
    const float* b1b = (const float*)d_in[7];
    const float* W2b = (const float*)d_in[8];
    const float* b2b = (const float*)d_in[9];
    const float* values   = (const float*)d_in[10];
    const int*   target   = (const int*)d_in[11];
    const int*   neighbor = (const int*)d_in[12];
    const int*   uids     = (const int*)d_in[13];
    const int*   pids     = (const int*)d_in[14];
    const int*   nids     = (const int*)d_in[15];
    float* out = (float*)d_out;

    static bool attr_set = false;
    if (!attr_set) {
        cudaFuncSetAttribute(k_layer1, cudaFuncAttributeMaxDynamicSharedMemorySize,
                             L1_SMEM_FLOATS * (int)sizeof(float));
        attr_set = true;
    }

    void *f1p, *f2p, *cntp, *countsp;
    cudaGetSymbolAddress(&f1p, g_flag1);
    cudaGetSymbolAddress(&f2p, g_flag2);
    cudaGetSymbolAddress(&cntp, g_cnt);
    cudaGetSymbolAddress(&countsp, g_counts);
    cudaMemsetAsync(f1p, 0, NN, 0);
    cudaMemsetAsync(f2p, 0, NN, 0);
    cudaMemsetAsync(cntp, 0, sizeof(int), 0);
    cudaMemsetAsync(countsp, 0, NN * sizeof(int), 0);

    k_flags<<<(BATCH + 255) / 256, 256>>>(uids, pids, nids);
    k_flag_neighbors<<<(NE + 255) / 256, 256>>>(target, neighbor);

    k_count<<<(NE + 255) / 256, 256>>>(target);
    k_scan1<<<NPARTS, 1024>>>();
    k_scan2<<<1, 256>>>();
    k_scan3<<<NPARTS, 1024>>>();
    k_scatter<<<(NE + 255) / 256, 256>>>(target, neighbor, values);
    k_build_list<<<(NN + 255) / 256, 256>>>();

    k_agg1_csr<<<(NN + 7) / 8, 256>>>(user_w, entity_w);
    k_layer1<<<(NN + 31) / 32, 256, L1_SMEM_FLOATS * sizeof(float)>>>(
        user_w, entity_w, W1a, b1a, W2a, b2a);
    k_agg2_csr<<<(3 * BATCH + 7) / 8, 256>>>(uids, pids, nids);
    k_layer2<<<(3 * BATCH + 7) / 8, 256>>>(uids, pids, nids, W1b, b1b, W2b, b2b);
    k_score<<<(BATCH + 7) / 8, 256>>>(user_w, entity_w, uids, pids, nids, out);
}